// round 4
// baseline (speedup 1.0000x reference)
#include <cuda_runtime.h>
#include <math.h>

#define Td 32
#define Bd 8
#define Id 512
#define Hd 512
#define H3 1536

// ---- output layout (concatenated tuple: v, h, dU, te, tE, outs) ----
#define OFF_V    0
#define OFF_H    4096
#define OFF_DU   8192
#define OFF_TE   2105344
#define OFF_TEE  2109440
#define OFF_OUTS 4206592

// ---- scratch (device globals; no allocation allowed) ----
__device__ float g_Wx[H3 * Id];         // 3 MB
__device__ float g_Wh[H3 * Hd];         // 3 MB
__device__ float g_xproj[Td * Bd * H3]; // 1.5 MB
__device__ float g_up[Hd * Hd];         // 1 MB
__device__ float g_lo[Hd * Hd];         // 1 MB
__device__ float g_h[2][Bd * Hd];       // ping-pong hidden state
__device__ float g_te[2][Bd * Hd];      // ping-pong eligibility trace e
__device__ float g_dvacc[Bd * Hd];      // sum_j alpha*dU*h for NEXT step

// ============================================================
// Weight norm: W = g * v / ||v||_row  for both x2h (1536x512) and h2h (1536x512)
// One warp per row. 3072 rows total.
// ============================================================
__global__ void k_wnorm(const float* __restrict__ x2h_v, const float* __restrict__ x2h_g,
                        const float* __restrict__ h2h_v, const float* __restrict__ h2h_g) {
    int w = (blockIdx.x * blockDim.x + threadIdx.x) >> 5;
    int lane = threadIdx.x & 31;
    const float* src; const float* g; float* dst; int row;
    if (w < H3) { src = x2h_v; g = x2h_g; dst = g_Wx; row = w; }
    else        { src = h2h_v; g = h2h_g; dst = g_Wh; row = w - H3; }
    const float* r = src + row * 512;
    float ss = 0.f;
    for (int k = lane; k < 512; k += 32) { float v = r[k]; ss = fmaf(v, v, ss); }
#pragma unroll
    for (int o = 16; o; o >>= 1) ss += __shfl_xor_sync(0xffffffffu, ss, o);
    float sc = g[row] / sqrtf(ss);
    for (int k = lane; k < 512; k += 32) dst[row * 512 + k] = r[k] * sc;
}

// ============================================================
// xproj = x @ Wx^T + b : M=256 (t*B+b), N=1536, K=512
// Block: 256 threads, one n per thread, 16 m-rows staged in smem.
// ============================================================
__global__ void __launch_bounds__(256) k_xproj(const float* __restrict__ x,
                                               const float* __restrict__ x2h_b) {
    __shared__ float xs[16 * 512]; // 32 KB
    int n = blockIdx.x * 256 + threadIdx.x;
    int m0 = blockIdx.y * 16;
    for (int idx = threadIdx.x; idx < 16 * 512; idx += 256)
        xs[idx] = x[(m0 + (idx >> 9)) * 512 + (idx & 511)];
    __syncthreads();
    float acc[16];
#pragma unroll
    for (int m = 0; m < 16; m++) acc[m] = 0.f;
    const float* wrow = g_Wx + n * 512;
    for (int k = 0; k < 512; k++) {
        float wv = wrow[k];
#pragma unroll
        for (int m = 0; m < 16; m++) acc[m] = fmaf(wv, xs[m * 512 + k], acc[m]);
    }
    float bb = x2h_b[n];
#pragma unroll
    for (int m = 0; m < 16; m++) g_xproj[(m0 + m) * H3 + n] = acc[m] + bb;
}

// ============================================================
// Clip bounds: up = relu(1-Wr)/(alpha+1e-5), lo = -relu(1+Wr)/(alpha+1e-5)
// Wr = Wh[H:2H], elementwise over H*H.
// ============================================================
__global__ void k_uplo(const float* __restrict__ alpha) {
    int idx = blockIdx.x * blockDim.x + threadIdx.x;
    float Wr = g_Wh[Hd * Hd + idx];
    float a = alpha[idx] + 1e-5f;
    g_up[idx] = fmaxf(1.0f - Wr, 0.f) / a;
    g_lo[idx] = -fmaxf(1.0f + Wr, 0.f) / a;
}

// ============================================================
// Init: copy initial states into place; seed dvacc = sum_j alpha*dU0*h0.
// One warp per (b,i): 4096 warps -> grid 512 x 256.
// ============================================================
__global__ void k_init(const float* __restrict__ h0, const float* __restrict__ v0,
                       const float* __restrict__ dU0, const float* __restrict__ te0,
                       const float* __restrict__ tE0, const float* __restrict__ alpha,
                       float* __restrict__ out) {
    float* out_v  = out + OFF_V;
    float* out_dU = out + OFF_DU;
    float* out_tE = out + OFF_TEE;
    int gt = blockIdx.x * blockDim.x + threadIdx.x;
    int w = gt >> 5, lane = gt & 31;
    int b = w >> 9, i = w & 511;
    const float* aRow = alpha + i * 512;
    int base = (b * 512 + i) * 512;
    float acc = 0.f;
    for (int j = lane; j < 512; j += 32) {
        float d = dU0[base + j];
        float e = tE0[base + j];
        out_dU[base + j] = d;
        out_tE[base + j] = e;
        acc = fmaf(aRow[j] * d, h0[b * 512 + j], acc);
    }
#pragma unroll
    for (int o = 16; o; o >>= 1) acc += __shfl_xor_sync(0xffffffffu, acc, o);
    if (lane == 0) g_dvacc[b * 512 + i] = acc;
    if (gt < 4096) {
        g_h[0][gt] = h0[gt];
        out_v[gt]  = v0[gt];
        g_te[0][gt] = te0[gt];
    }
}

// ============================================================
// Step B: hp = h@Wh^T (z and dv chunks only; r chunk is unused in reference),
// then z, v_n, hn. Warp i computes both dots for all 8 batches with h in smem.
// Grid: 64 blocks x 256 (8 warps -> 8 i per block).
// ============================================================
__global__ void __launch_bounds__(256) k_stepB(int t, int p,
        const float* __restrict__ h2h_b, float* __restrict__ out) {
    __shared__ float sh[Bd * Hd]; // 16 KB old h
    float* out_v    = out + OFF_V;
    float* out_outs = out + OFF_OUTS;
    const float* hOld = g_h[p];
    float* hNew = g_h[p ^ 1];
    for (int idx = threadIdx.x; idx < 4096; idx += 256) sh[idx] = hOld[idx];
    __syncthreads();
    int warp = threadIdx.x >> 5, lane = threadIdx.x & 31;
    int i = blockIdx.x * 8 + warp;
    float az[8], ad[8];
#pragma unroll
    for (int b = 0; b < 8; b++) { az[b] = 0.f; ad[b] = 0.f; }
    const float* wz = g_Wh + i * 512;
    const float* wd = g_Wh + (2 * Hd + i) * 512;
    for (int k = lane; k < 512; k += 32) {
        float a = wz[k], c = wd[k];
#pragma unroll
        for (int b = 0; b < 8; b++) {
            float hb = sh[b * 512 + k];
            az[b] = fmaf(a, hb, az[b]);
            ad[b] = fmaf(c, hb, ad[b]);
        }
    }
#pragma unroll
    for (int o = 16; o; o >>= 1) {
#pragma unroll
        for (int b = 0; b < 8; b++) {
            az[b] += __shfl_xor_sync(0xffffffffu, az[b], o);
            ad[b] += __shfl_xor_sync(0xffffffffu, ad[b], o);
        }
    }
    if (lane < 8) {
        int b = lane;
        float zh  = az[b] + h2h_b[i];
        float dvh = ad[b] + h2h_b[2 * Hd + i];
        int m = t * 8 + b;
        float zx  = g_xproj[m * H3 + i];
        float dvx = g_xproj[m * H3 + 2 * Hd + i];
        float z = 1.f / (1.f + expf(-(zx + zh)));
        float dv = dvx + dvh + g_dvacc[b * 512 + i];
        float vo = out_v[b * 512 + i];
        float vn = vo + z * (dv - vo);            // (1-z)*v + z*dv
        out_v[b * 512 + i] = vn;
        float hn = fmaxf(vn, 0.f);
        hNew[b * 512 + i] = hn;
        out_outs[m * 512 + i] = hn;
    }
}

// ============================================================
// Step C: per-block redundant mod-gate compute (cheap, avoids extra kernel),
// te_n on the fly, then the big (b,i,j) update of tE and dU IN PLACE in d_out,
// with the next step's dv matvec fused in (deterministic block reduction).
// Grid: 512 blocks (one i each) x 256 threads (2 j each, 8 b inner).
// ============================================================
__global__ void __launch_bounds__(256) k_stepC(int p,
        const float* __restrict__ alpha, const float* __restrict__ h2mod_w,
        const float* __restrict__ h2mod_b, const float* __restrict__ modU_w,
        const float* __restrict__ modU_b, float* __restrict__ out) {
    __shared__ float sh_hn[4096];
    __shared__ float sh_te[4096];
    __shared__ float s_mod[32];
    __shared__ float s_taue[8], s_tauE[8], s_tauU[8], s_mU[8];
    __shared__ float red[8][8];
    float* out_dU = out + OFF_DU;
    float* out_tE = out + OFF_TEE;
    const float* hn  = g_h[p ^ 1];   // new hidden (written by stepB)
    const float* hO  = g_h[p];       // old hidden (te update uses OLD h)
    const float* teO = g_te[p];
    float* teN = g_te[p ^ 1];
    int tid = threadIdx.x;
    for (int idx = tid; idx < 4096; idx += 256) sh_hn[idx] = hn[idx];
    __syncthreads();
    int warp = tid >> 5, lane = tid & 31;
    // mod[b,m] = hn[b]·h2mod_w[m] + h2mod_b[m]; warp = b, 4 dots each
    {
        int b = warp;
#pragma unroll
        for (int m = 0; m < 4; m++) {
            float a = 0.f;
            const float* wrow = h2mod_w + m * 512;
            for (int k = lane; k < 512; k += 32)
                a = fmaf(sh_hn[b * 512 + k], wrow[k], a);
#pragma unroll
            for (int o = 16; o; o >>= 1) a += __shfl_xor_sync(0xffffffffu, a, o);
            if (lane == 0) s_mod[b * 4 + m] = a + h2mod_b[m];
        }
    }
    __syncthreads();
    if (tid < 8) {
        float m0 = s_mod[tid * 4 + 0], m1 = s_mod[tid * 4 + 1];
        float m2 = s_mod[tid * 4 + 2], m3 = s_mod[tid * 4 + 3];
        s_taue[tid] = 1.f / (1.f + expf(-m0));
        s_tauE[tid] = 1.f / (1.f + expf(-m1));
        s_tauU[tid] = 1.f / (1.f + expf(-m2));
        s_mU[tid]   = fmaxf(m3, 0.f);
    }
    __syncthreads();
    // te_n (same in every block; block 0 persists it for next step)
    for (int idx = tid; idx < 4096; idx += 256) {
        int b = idx >> 9;
        float te = teO[idx];
        float tn = te + s_taue[b] * (hO[idx] - te);
        sh_te[idx] = tn;
        if (blockIdx.x == 0) teN[idx] = tn;
    }
    __syncthreads();
    // main update for row i = blockIdx.x, j covered by this block
    int i = blockIdx.x;
    float acc[8];
#pragma unroll
    for (int b = 0; b < 8; b++) acc[b] = 0.f;
#pragma unroll
    for (int jh = 0; jh < 2; jh++) {
        int j = tid + jh * 256;
        int cij = i * 512 + j;
        float a  = alpha[cij];
        float wv = modU_w[cij];
        float bv = modU_b[cij];
        float lo = g_lo[cij];
        float up = g_up[cij];
#pragma unroll
        for (int b = 0; b < 8; b++) {
            int idx = (b * 512 + i) * 512 + j;
            float dU = out_dU[idx];
            float tE = out_tE[idx];
            float hni = sh_hn[b * 512 + i];
            float hnj = sh_hn[b * 512 + j];
            float tei = sh_te[b * 512 + i];
            float tej = sh_te[b * 512 + j];
            float outer = hni * tej - tei * hnj;
            float tEn = tE + s_tauE[b] * (outer - tE);     // (1-tauE)*tE + tauE*outer
            float y = fmaf(s_mU[b], wv, bv);
            float s = (y > 0.5f) ? (y - 0.5f) : ((y < -0.5f) ? (y + 0.5f) : 0.f);
            float dUn = dU + s_tauU[b] * (s * tEn - dU);
            dUn = fminf(fmaxf(dUn, lo), up);
            out_tE[idx] = tEn;
            out_dU[idx] = dUn;
            acc[b] = fmaf(a * dUn, hnj, acc[b]);           // fused next-step matvec
        }
    }
    // deterministic reduction of acc over the block -> g_dvacc[b,i]
#pragma unroll
    for (int b = 0; b < 8; b++) {
        float v = acc[b];
#pragma unroll
        for (int o = 16; o; o >>= 1) v += __shfl_xor_sync(0xffffffffu, v, o);
        if (lane == 0) red[warp][b] = v;
    }
    __syncthreads();
    if (tid < 8) {
        float s2 = 0.f;
#pragma unroll
        for (int w2 = 0; w2 < 8; w2++) s2 += red[w2][tid];
        g_dvacc[tid * 512 + i] = s2;
    }
}

// ============================================================
// Final: copy last h and te into output slots (T=32 even -> parity 0).
// ============================================================
__global__ void k_fin(float* __restrict__ out) {
    int idx = blockIdx.x * blockDim.x + threadIdx.x;
    if (idx < 4096) {
        out[OFF_H + idx]  = g_h[0][idx];
        out[OFF_TE + idx] = g_te[0][idx];
    }
}

extern "C" void kernel_launch(void* const* d_in, const int* in_sizes, int n_in,
                              void* d_out, int out_size) {
    const float* x       = (const float*)d_in[0];
    const float* h0      = (const float*)d_in[1];
    const float* v0      = (const float*)d_in[2];
    const float* dU0     = (const float*)d_in[3];
    const float* te0     = (const float*)d_in[4];
    const float* tE0     = (const float*)d_in[5];
    const float* x2h_v   = (const float*)d_in[6];
    const float* x2h_g   = (const float*)d_in[7];
    const float* x2h_b   = (const float*)d_in[8];
    const float* h2h_v   = (const float*)d_in[9];
    const float* h2h_g   = (const float*)d_in[10];
    const float* h2h_b   = (const float*)d_in[11];
    const float* alpha   = (const float*)d_in[12];
    const float* h2mod_w = (const float*)d_in[13];
    const float* h2mod_b = (const float*)d_in[14];
    const float* modU_w  = (const float*)d_in[15];
    const float* modU_b  = (const float*)d_in[16];
    float* out = (float*)d_out;

    k_wnorm<<<384, 256>>>(x2h_v, x2h_g, h2h_v, h2h_g);
    k_xproj<<<dim3(6, 16), 256>>>(x, x2h_b);
    k_uplo<<<1024, 256>>>(alpha);
    k_init<<<512, 256>>>(h0, v0, dU0, te0, tE0, alpha, out);
    for (int t = 0; t < Td; t++) {
        int p = t & 1;
        k_stepB<<<64, 256>>>(t, p, h2h_b, out);
        k_stepC<<<512, 256>>>(p, alpha, h2mod_w, h2mod_b, modU_w, modU_b, out);
    }
    k_fin<<<16, 256>>>(out);
}

// round 5
// speedup vs baseline: 2.1640x; 2.1640x over previous
#include <cuda_runtime.h>
#include <math.h>

#define Td 32
#define Bd 8
#define Id 512
#define Hd 512
#define H3 1536
#define NBLK 512

// ---- output layout (concatenated tuple: v, h, dU, te, tE, outs) ----
#define OFF_V    0
#define OFF_H    4096
#define OFF_DU   8192
#define OFF_TE   2105344
#define OFF_TEE  2109440
#define OFF_OUTS 4206592

// ---- scratch (device globals; no allocation allowed) ----
__device__ float g_Wx[H3 * Id];         // 3 MB
__device__ float g_Wh[H3 * Hd];         // 3 MB
__device__ float g_xproj[Td * Bd * H3]; // 1.5 MB
__device__ float g_hbuf[2][Bd * Hd];    // ping-pong hidden state
__device__ unsigned g_count = 0;
__device__ unsigned g_gen = 0;

// ============================================================
// Weight norm: W = g * v / ||v||_row  (x2h 1536x512, h2h 1536x512)
// ============================================================
__global__ void k_wnorm(const float* __restrict__ x2h_v, const float* __restrict__ x2h_g,
                        const float* __restrict__ h2h_v, const float* __restrict__ h2h_g) {
    int w = (blockIdx.x * blockDim.x + threadIdx.x) >> 5;
    int lane = threadIdx.x & 31;
    const float* src; const float* g; float* dst; int row;
    if (w < H3) { src = x2h_v; g = x2h_g; dst = g_Wx; row = w; }
    else        { src = h2h_v; g = h2h_g; dst = g_Wh; row = w - H3; }
    const float* r = src + row * 512;
    float ss = 0.f;
    for (int k = lane; k < 512; k += 32) { float v = r[k]; ss = fmaf(v, v, ss); }
#pragma unroll
    for (int o = 16; o; o >>= 1) ss += __shfl_xor_sync(0xffffffffu, ss, o);
    float sc = g[row] / sqrtf(ss);
    for (int k = lane; k < 512; k += 32) dst[row * 512 + k] = r[k] * sc;
}

// ============================================================
// xproj = x @ Wx^T + b : M=256, N=1536, K=512
// ============================================================
__global__ void __launch_bounds__(256) k_xproj(const float* __restrict__ x,
                                               const float* __restrict__ x2h_b) {
    __shared__ float xs[16 * 512]; // 32 KB
    int n = blockIdx.x * 256 + threadIdx.x;
    int m0 = blockIdx.y * 16;
    for (int idx = threadIdx.x; idx < 16 * 512; idx += 256)
        xs[idx] = x[(m0 + (idx >> 9)) * 512 + (idx & 511)];
    __syncthreads();
    float acc[16];
#pragma unroll
    for (int m = 0; m < 16; m++) acc[m] = 0.f;
    const float* wrow = g_Wx + n * 512;
    for (int k = 0; k < 512; k++) {
        float wv = wrow[k];
#pragma unroll
        for (int m = 0; m < 16; m++) acc[m] = fmaf(wv, xs[m * 512 + k], acc[m]);
    }
    float bb = x2h_b[n];
#pragma unroll
    for (int m = 0; m < 16; m++) g_xproj[(m0 + m) * H3 + n] = acc[m] + bb;
}

// ============================================================
// Grid-wide software barrier (all NBLK blocks co-resident).
// Release: threadfence before arrive. Acquire: threadfence after
// (gpu-scope fence -> CCTL.IVALL invalidates L1D, so post-barrier
// loads see other blocks' writes).
// ============================================================
__device__ __forceinline__ void grid_bar(unsigned &lgen) {
    __syncthreads();
    __threadfence();
    if (threadIdx.x == 0) {
        unsigned target = lgen + 1u;
        unsigned a = atomicAdd(&g_count, 1u);
        if (a == NBLK - 1u) {
            g_count = 0u;
            __threadfence();
            atomicAdd(&g_gen, 1u);
        } else {
            volatile unsigned* vg = &g_gen;
            while ((*vg - lgen) == 0u) { }
        }
        lgen = target;
    }
    __syncthreads();
    __threadfence();
}

__device__ __forceinline__ float sigmoidf_(float x) { return 1.f / (1.f + expf(-x)); }

// ============================================================
// Persistent scan kernel. Block i owns dU[:,i,:], tE[:,i,:] in SMEM for
// the entire scan; te and the per-thread h values live in registers.
// One grid barrier per step (hn produce -> hn consume).
// Thread tid handles j = {2*tid, 2*tid+1} (float2), b = 0..7 inner.
// ============================================================
__global__ void __launch_bounds__(256, 4) k_scan(
    const float* __restrict__ h0, const float* __restrict__ v0,
    const float* __restrict__ dU0, const float* __restrict__ te0,
    const float* __restrict__ tE0, const float* __restrict__ alpha,
    const float* __restrict__ h2h_b, const float* __restrict__ h2mod_w,
    const float* __restrict__ h2mod_b, const float* __restrict__ modU_w,
    const float* __restrict__ modU_b, float* __restrict__ out)
{
    __shared__ float2 sdU2[8 * 256];   // 16 KB persistent state
    __shared__ float2 stE2[8 * 256];   // 16 KB persistent state
    __shared__ float2 salpha2[256], swv2[256], sbv2[256], slo2[256], sup2[256]; // 10 KB
    __shared__ float sv[8], s_dvacc[8], s_hni[8], s_tei[8];
    __shared__ float s_taue[8], s_tauE[8], s_tauU[8], s_mU[8];
    __shared__ float s_red[8][8];

    const int i = blockIdx.x;
    const int tid = threadIdx.x;
    const int wb = tid >> 5, lane = tid & 31;
    unsigned lgen = g_gen;   // stable at launch start (no barrier in flight)

    // ---- per-row constants into smem ----
    float2 a2 = ((const float2*)(alpha + i * Hd))[tid];
    salpha2[tid] = a2;
    swv2[tid] = ((const float2*)(modU_w + i * Hd))[tid];
    sbv2[tid] = ((const float2*)(modU_b + i * Hd))[tid];
    {
        float2 wr = ((const float2*)(g_Wh + (Hd + i) * Hd))[tid]; // Wr row i
        float ax = a2.x + 1e-5f, ay = a2.y + 1e-5f;
        float2 up2, lo2;
        up2.x = fmaxf(1.f - wr.x, 0.f) / ax;  up2.y = fmaxf(1.f - wr.y, 0.f) / ay;
        lo2.x = -fmaxf(1.f + wr.x, 0.f) / ax; lo2.y = -fmaxf(1.f + wr.y, 0.f) / ay;
        sup2[tid] = up2; slo2[tid] = lo2;
    }

    // ---- state init ----
    float2 te[8];   // trace e for (b, my j-pair)
    float2 hj[8];   // h_t[b, my j-pair] (carried across the barrier)
    float acc[8];
#pragma unroll
    for (int u = 0; u < 8; u++) {
        float2 d2 = ((const float2*)(dU0 + (u * Hd + i) * Hd))[tid];
        sdU2[u * 256 + tid] = d2;
        stE2[u * 256 + tid] = ((const float2*)(tE0 + (u * Hd + i) * Hd))[tid];
        te[u] = ((const float2*)(te0 + u * Hd))[tid];
        hj[u] = ((const float2*)(h0 + u * Hd))[tid];
        acc[u] = a2.x * d2.x * hj[u].x + a2.y * d2.y * hj[u].y;
    }
    if (tid < 8) sv[tid] = v0[tid * Hd + i];

    // dvacc_0 = sum_j alpha*dU0*h0 (block reduce, deterministic)
#pragma unroll
    for (int u = 0; u < 8; u++) {
        float v = acc[u];
#pragma unroll
        for (int o = 16; o; o >>= 1) v += __shfl_xor_sync(0xffffffffu, v, o);
        if (lane == 0) s_red[wb][u] = v;
    }
    __syncthreads();
    if (tid < 8) {
        float s = 0.f;
#pragma unroll
        for (int w2 = 0; w2 < 8; w2++) s += s_red[w2][tid];
        s_dvacc[tid] = s;
    }
    __syncthreads();

    const float* hc = h0;                 // h_t (read-only this step)
    const float bz = h2h_b[i];
    const float bd = h2h_b[2 * Hd + i];

    for (int t = 0; t < Td; t++) {
        float* hn_buf = g_hbuf[t & 1];

        // ---- phase A: hn[b,i] for own i (warp wb = batch b) ----
        {
            const float* wz = g_Wh + i * Hd;
            const float* wd = g_Wh + (2 * Hd + i) * Hd;
            const float* hb = hc + wb * Hd;
            float az = 0.f, ad = 0.f;
            for (int k = lane; k < Hd; k += 32) {
                float h = hb[k];
                az = fmaf(wz[k], h, az);
                ad = fmaf(wd[k], h, ad);
            }
#pragma unroll
            for (int o = 16; o; o >>= 1) {
                az += __shfl_xor_sync(0xffffffffu, az, o);
                ad += __shfl_xor_sync(0xffffffffu, ad, o);
            }
            if (lane == 0) {
                const float* xp = g_xproj + (t * Bd + wb) * H3;
                float z  = sigmoidf_(xp[i] + az + bz);
                float dv = xp[2 * Hd + i] + ad + bd + s_dvacc[wb];
                float vo = sv[wb];
                float vn = vo + z * (dv - vo);         // (1-z)v + z dv
                sv[wb] = vn;
                float hn = fmaxf(vn, 0.f);
                s_hni[wb] = hn;
                hn_buf[wb * Hd + i] = hn;
                out[OFF_OUTS + (t * Bd + wb) * Hd + i] = hn;
            }
        }

        grid_bar(lgen);   // hn visible everywhere; h_t values we still need are in hj[] regs

        // ---- gates: mod = hn @ h2mod_w^T + b (redundant per block, warp=b) ----
        {
            const float* hnb = hn_buf + wb * Hd;
            float m0 = 0.f, m1 = 0.f, m2 = 0.f, m3 = 0.f;
            for (int k = lane; k < Hd; k += 32) {
                float h = hnb[k];
                m0 = fmaf(h2mod_w[k], h, m0);
                m1 = fmaf(h2mod_w[Hd + k], h, m1);
                m2 = fmaf(h2mod_w[2 * Hd + k], h, m2);
                m3 = fmaf(h2mod_w[3 * Hd + k], h, m3);
            }
#pragma unroll
            for (int o = 16; o; o >>= 1) {
                m0 += __shfl_xor_sync(0xffffffffu, m0, o);
                m1 += __shfl_xor_sync(0xffffffffu, m1, o);
                m2 += __shfl_xor_sync(0xffffffffu, m2, o);
                m3 += __shfl_xor_sync(0xffffffffu, m3, o);
            }
            if (lane == 0) {
                s_taue[wb] = sigmoidf_(m0 + h2mod_b[0]);
                s_tauE[wb] = sigmoidf_(m1 + h2mod_b[1]);
                s_tauU[wb] = sigmoidf_(m2 + h2mod_b[2]);
                s_mU[wb]   = fmaxf(m3 + h2mod_b[3], 0.f);
            }
        }
        __syncthreads();

        // ---- te update (register-local; uses OLD h carried in hj) ----
#pragma unroll
        for (int u = 0; u < 8; u++) {
            float taue = s_taue[u];
            float2 t2 = te[u], h2 = hj[u];
            t2.x += taue * (h2.x - t2.x);
            t2.y += taue * (h2.y - t2.y);
            te[u] = t2;
        }
        if (tid == (i >> 1)) {           // owner of j==i publishes te_n[b,i]
#pragma unroll
            for (int u = 0; u < 8; u++)
                s_tei[u] = (i & 1) ? te[u].y : te[u].x;
        }
        __syncthreads();

        // ---- main state update + fused dv matvec ----
        {
            float2 w2 = swv2[tid], b2 = sbv2[tid], l2 = slo2[tid], u2_ = sup2[tid];
            float2 aa = salpha2[tid];
#pragma unroll
            for (int u = 0; u < 8; u++) {
                float2 hnj = ((const float2*)(hn_buf + u * Hd))[tid];
                hj[u] = hnj;                     // becomes "old h" next step
                float hni = s_hni[u], tei = s_tei[u];
                float tauE = s_tauE[u], tauU = s_tauU[u], mU = s_mU[u];
                float2 tn = te[u];
                float ox = hni * tn.x - tei * hnj.x;
                float oy = hni * tn.y - tei * hnj.y;
                float2 E = stE2[u * 256 + tid];
                E.x += tauE * (ox - E.x);
                E.y += tauE * (oy - E.y);
                stE2[u * 256 + tid] = E;
                float yx = fmaf(mU, w2.x, b2.x);
                float yy = fmaf(mU, w2.y, b2.y);
                float sx = (yx > 0.5f) ? yx - 0.5f : ((yx < -0.5f) ? yx + 0.5f : 0.f);
                float sy = (yy > 0.5f) ? yy - 0.5f : ((yy < -0.5f) ? yy + 0.5f : 0.f);
                float2 D = sdU2[u * 256 + tid];
                D.x += tauU * (sx * E.x - D.x);
                D.y += tauU * (sy * E.y - D.y);
                D.x = fminf(fmaxf(D.x, l2.x), u2_.x);
                D.y = fminf(fmaxf(D.y, l2.y), u2_.y);
                sdU2[u * 256 + tid] = D;
                acc[u] = aa.x * D.x * hnj.x + aa.y * D.y * hnj.y;
            }
        }
        // dvacc for next step (block-local deterministic reduce)
#pragma unroll
        for (int u = 0; u < 8; u++) {
            float v = acc[u];
#pragma unroll
            for (int o = 16; o; o >>= 1) v += __shfl_xor_sync(0xffffffffu, v, o);
            if (lane == 0) s_red[wb][u] = v;
        }
        __syncthreads();
        if (tid < 8) {
            float s = 0.f;
#pragma unroll
            for (int w2i = 0; w2i < 8; w2i++) s += s_red[w2i][tid];
            s_dvacc[tid] = s;
        }
        __syncthreads();

        hc = hn_buf;
    }

    // ---- epilogue: dump final state ----
    if (tid < 8) {
        out[OFF_V + tid * Hd + i] = sv[tid];
        out[OFF_H + tid * Hd + i] = s_hni[tid];
    }
#pragma unroll
    for (int u = 0; u < 8; u++) {
        ((float2*)(out + OFF_DU  + (u * Hd + i) * Hd))[tid] = sdU2[u * 256 + tid];
        ((float2*)(out + OFF_TEE + (u * Hd + i) * Hd))[tid] = stE2[u * 256 + tid];
    }
    if (i == 0) {
#pragma unroll
        for (int u = 0; u < 8; u++)
            ((float2*)(out + OFF_TE + u * Hd))[tid] = te[u];
    }
}

extern "C" void kernel_launch(void* const* d_in, const int* in_sizes, int n_in,
                              void* d_out, int out_size) {
    const float* x       = (const float*)d_in[0];
    const float* h0      = (const float*)d_in[1];
    const float* v0      = (const float*)d_in[2];
    const float* dU0     = (const float*)d_in[3];
    const float* te0     = (const float*)d_in[4];
    const float* tE0     = (const float*)d_in[5];
    const float* x2h_v   = (const float*)d_in[6];
    const float* x2h_g   = (const float*)d_in[7];
    const float* x2h_b   = (const float*)d_in[8];
    const float* h2h_v   = (const float*)d_in[9];
    const float* h2h_g   = (const float*)d_in[10];
    const float* h2h_b   = (const float*)d_in[11];
    const float* alpha   = (const float*)d_in[12];
    const float* h2mod_w = (const float*)d_in[13];
    const float* h2mod_b = (const float*)d_in[14];
    const float* modU_w  = (const float*)d_in[15];
    const float* modU_b  = (const float*)d_in[16];
    float* out = (float*)d_out;

    k_wnorm<<<384, 256>>>(x2h_v, x2h_g, h2h_v, h2h_g);
    k_xproj<<<dim3(6, 16), 256>>>(x, x2h_b);
    k_scan<<<NBLK, 256>>>(h0, v0, dU0, te0, tE0, alpha, h2h_b,
                          h2mod_w, h2mod_b, modU_w, modU_b, out);
}

// round 6
// speedup vs baseline: 2.9603x; 1.3680x over previous
#include <cuda_runtime.h>
#include <math.h>

#define Td 32
#define Bd 8
#define Id 512
#define Hd 512
#define H3 1536
#define NBLK 512

// ---- output layout (concatenated tuple: v, h, dU, te, tE, outs) ----
#define OFF_V    0
#define OFF_H    4096
#define OFF_DU   8192
#define OFF_TE   2105344
#define OFF_TEE  2109440
#define OFF_OUTS 4206592

// ---- scratch (device globals; no allocation allowed) ----
__device__ float g_xproj[Td * Bd * H3]; // 1.5 MB
__device__ float g_hbuf[2][Bd * Hd];    // ping-pong hidden state
__device__ unsigned g_count = 0;
__device__ unsigned g_flag[16 * 32];    // 16 broadcast flags, 128B apart

// ============================================================
// xproj = x @ (wnorm(x2h_v,g))^T + b : M=256, N=1536, K=512.
// Weight-norm fused: ss accumulated from the same loaded weights.
// Grid (6, 32): 256 n per block, 8 m rows per block.
// ============================================================
__global__ void __launch_bounds__(256) k_xproj(const float* __restrict__ x,
                                               const float* __restrict__ x2h_v,
                                               const float* __restrict__ x2h_g,
                                               const float* __restrict__ x2h_b) {
    __shared__ float xs[8 * 512]; // 16 KB
    int n = blockIdx.x * 256 + threadIdx.x;
    int m0 = blockIdx.y * 8;
    for (int idx = threadIdx.x; idx < 8 * 512; idx += 256)
        xs[idx] = x[(m0 + (idx >> 9)) * 512 + (idx & 511)];
    __syncthreads();
    float acc[8];
#pragma unroll
    for (int m = 0; m < 8; m++) acc[m] = 0.f;
    float ss = 0.f;
    const float4* wrow4 = (const float4*)(x2h_v + n * 512);
    for (int c = 0; c < 128; c++) {
        float4 w4 = wrow4[c];
        ss = fmaf(w4.x, w4.x, ss); ss = fmaf(w4.y, w4.y, ss);
        ss = fmaf(w4.z, w4.z, ss); ss = fmaf(w4.w, w4.w, ss);
#pragma unroll
        for (int m = 0; m < 8; m++) {
            float4 x4 = ((const float4*)(xs + m * 512))[c];
            acc[m] = fmaf(w4.x, x4.x, acc[m]);
            acc[m] = fmaf(w4.y, x4.y, acc[m]);
            acc[m] = fmaf(w4.z, x4.z, acc[m]);
            acc[m] = fmaf(w4.w, x4.w, acc[m]);
        }
    }
    float sc = x2h_g[n] * rsqrtf(ss);
    float bb = x2h_b[n];
#pragma unroll
    for (int m = 0; m < 8; m++)
        g_xproj[(m0 + m) * H3 + n] = fmaf(acc[m], sc, bb);
}

// ============================================================
// Grid-wide software barrier; arrival on one counter, release broadcast
// over 16 padded flag words (32 pollers each).
// ============================================================
__device__ __forceinline__ void grid_bar(unsigned &lgen, int fidx) {
    __syncthreads();
    __threadfence();
    if (threadIdx.x == 0) {
        unsigned a = atomicAdd(&g_count, 1u);
        if (a == NBLK - 1u) {
            g_count = 0u;
            __threadfence();
#pragma unroll
            for (int f = 0; f < 16; f++)
                ((volatile unsigned*)g_flag)[f * 32] = lgen + 1u;
        } else {
            volatile unsigned* vf = &g_flag[fidx * 32];
            while (*vf == lgen) { }
        }
        lgen += 1u;
    }
    __syncthreads();
    __threadfence();
}

__device__ __forceinline__ float sigf(float x) { return 1.f / (1.f + __expf(-x)); }

// ============================================================
// Persistent scan. Block i owns dU[:,i,:], tE[:,i,:] in dynamic SMEM for
// all 32 steps. Step-invariant data (own Wh rows, h2mod_w, per-row consts)
// preloaded into SMEM (survives the per-step L1 invalidation).
// ============================================================
__global__ void __launch_bounds__(256, 4) k_scan(
    const float* __restrict__ h0, const float* __restrict__ v0,
    const float* __restrict__ dU0, const float* __restrict__ te0,
    const float* __restrict__ tE0, const float* __restrict__ alpha,
    const float* __restrict__ h2h_v, const float* __restrict__ h2h_g,
    const float* __restrict__ h2h_b, const float* __restrict__ h2mod_w,
    const float* __restrict__ h2mod_b, const float* __restrict__ modU_w,
    const float* __restrict__ modU_b, float* __restrict__ out)
{
    extern __shared__ float sm[];
    float* sdU  = sm;             // 4096
    float* stE  = sdU + 4096;     // 4096
    float* s_al = stE + 4096;     // 512
    float* s_wv = s_al + 512;     // 512
    float* s_bv = s_wv + 512;     // 512
    float* s_lo = s_bv + 512;     // 512
    float* s_up = s_lo + 512;     // 512
    float* s_wz = s_up + 512;     // 512 (normalized Wh row i)
    float* s_wd = s_wz + 512;     // 512 (normalized Wh row 2H+i)
    float* s_mw = s_wd + 512;     // 2048 (h2mod_w, 4x512)
    // total 13824 floats = 55296 B

    __shared__ float sv[8], s_dvacc[8], s_hni[8], s_tei[8];
    __shared__ float s_taue[8], s_tauE[8], s_tauU[8], s_mU[8];
    __shared__ float s_red[8][8];
    __shared__ float s_sc[3];

    const int i = blockIdx.x;
    const int tid = threadIdx.x;
    const int wb = tid >> 5, lane = tid & 31;
    const int fidx = blockIdx.x & 15;
    unsigned lgen = ((volatile unsigned*)g_flag)[fidx * 32];

    const float mb0 = h2mod_b[0], mb1 = h2mod_b[1];
    const float mb2 = h2mod_b[2], mb3 = h2mod_b[3];
    const float bz = h2h_b[i];
    const float bd = h2h_b[2 * Hd + i];

    // ---- inline weight-norm of own 3 h2h rows ----
    float2 vz2 = ((const float2*)(h2h_v + i * Hd))[tid];
    float2 vr2 = ((const float2*)(h2h_v + (Hd + i) * Hd))[tid];
    float2 vd2 = ((const float2*)(h2h_v + (2 * Hd + i) * Hd))[tid];
    {
        float sz = vz2.x * vz2.x + vz2.y * vz2.y;
        float sr = vr2.x * vr2.x + vr2.y * vr2.y;
        float sd = vd2.x * vd2.x + vd2.y * vd2.y;
#pragma unroll
        for (int o = 16; o; o >>= 1) {
            sz += __shfl_xor_sync(0xffffffffu, sz, o);
            sr += __shfl_xor_sync(0xffffffffu, sr, o);
            sd += __shfl_xor_sync(0xffffffffu, sd, o);
        }
        if (lane == 0) { s_red[wb][0] = sz; s_red[wb][1] = sr; s_red[wb][2] = sd; }
    }
    __syncthreads();
    if (tid < 3) {
        float s = 0.f;
#pragma unroll
        for (int w2 = 0; w2 < 8; w2++) s += s_red[w2][tid];
        int row = (tid == 0) ? i : ((tid == 1) ? (Hd + i) : (2 * Hd + i));
        s_sc[tid] = h2h_g[row] * rsqrtf(s);
    }
    __syncthreads();
    {
        float scz = s_sc[0], scr = s_sc[1], scd = s_sc[2];
        ((float2*)s_wz)[tid] = make_float2(vz2.x * scz, vz2.y * scz);
        ((float2*)s_wd)[tid] = make_float2(vd2.x * scd, vd2.y * scd);
        float2 a2 = ((const float2*)(alpha + i * Hd))[tid];
        ((float2*)s_al)[tid] = a2;
        ((float2*)s_wv)[tid] = ((const float2*)(modU_w + i * Hd))[tid];
        ((float2*)s_bv)[tid] = ((const float2*)(modU_b + i * Hd))[tid];
        float wrx = vr2.x * scr, wry = vr2.y * scr;
        float ax = a2.x + 1e-5f, ay = a2.y + 1e-5f;
        ((float2*)s_up)[tid] = make_float2(fmaxf(1.f - wrx, 0.f) / ax,
                                           fmaxf(1.f - wry, 0.f) / ay);
        ((float2*)s_lo)[tid] = make_float2(-fmaxf(1.f + wrx, 0.f) / ax,
                                           -fmaxf(1.f + wry, 0.f) / ay);
    }
    for (int idx = tid; idx < 2048; idx += 256) s_mw[idx] = h2mod_w[idx];

    // ---- state init ----
    float2 te[8], hj[8];
    float acc[8];
    {
        float2 a2 = ((const float2*)s_al)[tid];
#pragma unroll
        for (int u = 0; u < 8; u++) {
            float2 d2 = ((const float2*)(dU0 + (u * Hd + i) * Hd))[tid];
            ((float2*)sdU)[u * 256 + tid] = d2;
            ((float2*)stE)[u * 256 + tid] = ((const float2*)(tE0 + (u * Hd + i) * Hd))[tid];
            te[u] = ((const float2*)(te0 + u * Hd))[tid];
            hj[u] = ((const float2*)(h0 + u * Hd))[tid];
            acc[u] = a2.x * d2.x * hj[u].x + a2.y * d2.y * hj[u].y;
        }
    }
    if (tid < 8) sv[tid] = v0[tid * Hd + i];
#pragma unroll
    for (int u = 0; u < 8; u++) {
        float v = acc[u];
#pragma unroll
        for (int o = 16; o; o >>= 1) v += __shfl_xor_sync(0xffffffffu, v, o);
        if (lane == 0) s_red[wb][u] = v;
    }
    __syncthreads();
    if (tid < 8) {
        float s = 0.f;
#pragma unroll
        for (int w2 = 0; w2 < 8; w2++) s += s_red[w2][tid];
        s_dvacc[tid] = s;
    }
    __syncthreads();

    const float* hc = h0;

    for (int t = 0; t < Td; t++) {
        float* hn_buf = g_hbuf[t & 1];

        // ---- phase A: hn[b,i] (warp wb = batch b); all smem weights ----
        {
            float xpz = 0.f, xpd = 0.f, dvac = 0.f, vo = 0.f;
            if (lane == 0) {
                const float* xp = g_xproj + (t * Bd + wb) * H3;
                xpz = xp[i]; xpd = xp[2 * Hd + i];   // L2 loads overlap the dot
                dvac = s_dvacc[wb]; vo = sv[wb];
            }
            const float4* hb4 = (const float4*)(hc + wb * Hd);
            float az = 0.f, ad = 0.f;
#pragma unroll
            for (int it = 0; it < 4; it++) {
                float4 h4 = hb4[lane + 32 * it];
                float4 a4 = ((const float4*)s_wz)[lane + 32 * it];
                float4 c4 = ((const float4*)s_wd)[lane + 32 * it];
                az = fmaf(a4.x, h4.x, az); az = fmaf(a4.y, h4.y, az);
                az = fmaf(a4.z, h4.z, az); az = fmaf(a4.w, h4.w, az);
                ad = fmaf(c4.x, h4.x, ad); ad = fmaf(c4.y, h4.y, ad);
                ad = fmaf(c4.z, h4.z, ad); ad = fmaf(c4.w, h4.w, ad);
            }
#pragma unroll
            for (int o = 16; o; o >>= 1) {
                az += __shfl_xor_sync(0xffffffffu, az, o);
                ad += __shfl_xor_sync(0xffffffffu, ad, o);
            }
            if (lane == 0) {
                float z  = sigf(xpz + az + bz);
                float dv = xpd + ad + bd + dvac;
                float vn = vo + z * (dv - vo);
                sv[wb] = vn;
                float hn = fmaxf(vn, 0.f);
                s_hni[wb] = hn;
                hn_buf[wb * Hd + i] = hn;
                out[OFF_OUTS + (t * Bd + wb) * Hd + i] = hn;
            }
        }

        grid_bar(lgen, fidx);

        // ---- gates (redundant per block; weights in smem) ----
        {
            const float4* hn4 = (const float4*)(hn_buf + wb * Hd);
            float m0 = 0.f, m1 = 0.f, m2 = 0.f, m3 = 0.f;
#pragma unroll
            for (int it = 0; it < 4; it++) {
                float4 h4 = hn4[lane + 32 * it];
                float4 w0 = ((const float4*)(s_mw + 0 * Hd))[lane + 32 * it];
                float4 w1 = ((const float4*)(s_mw + 1 * Hd))[lane + 32 * it];
                float4 w2 = ((const float4*)(s_mw + 2 * Hd))[lane + 32 * it];
                float4 w3 = ((const float4*)(s_mw + 3 * Hd))[lane + 32 * it];
                m0 = fmaf(w0.x, h4.x, m0); m0 = fmaf(w0.y, h4.y, m0);
                m0 = fmaf(w0.z, h4.z, m0); m0 = fmaf(w0.w, h4.w, m0);
                m1 = fmaf(w1.x, h4.x, m1); m1 = fmaf(w1.y, h4.y, m1);
                m1 = fmaf(w1.z, h4.z, m1); m1 = fmaf(w1.w, h4.w, m1);
                m2 = fmaf(w2.x, h4.x, m2); m2 = fmaf(w2.y, h4.y, m2);
                m2 = fmaf(w2.z, h4.z, m2); m2 = fmaf(w2.w, h4.w, m2);
                m3 = fmaf(w3.x, h4.x, m3); m3 = fmaf(w3.y, h4.y, m3);
                m3 = fmaf(w3.z, h4.z, m3); m3 = fmaf(w3.w, h4.w, m3);
            }
#pragma unroll
            for (int o = 16; o; o >>= 1) {
                m0 += __shfl_xor_sync(0xffffffffu, m0, o);
                m1 += __shfl_xor_sync(0xffffffffu, m1, o);
                m2 += __shfl_xor_sync(0xffffffffu, m2, o);
                m3 += __shfl_xor_sync(0xffffffffu, m3, o);
            }
            if (lane == 0) {
                s_taue[wb] = sigf(m0 + mb0);
                s_tauE[wb] = sigf(m1 + mb1);
                s_tauU[wb] = sigf(m2 + mb2);
                s_mU[wb]   = fmaxf(m3 + mb3, 0.f);
            }
        }
        __syncthreads();

        // ---- te update (register-local; uses OLD h in hj) ----
#pragma unroll
        for (int u = 0; u < 8; u++) {
            float taue = s_taue[u];
            float2 t2 = te[u], h2 = hj[u];
            t2.x += taue * (h2.x - t2.x);
            t2.y += taue * (h2.y - t2.y);
            te[u] = t2;
        }
        if (tid == (i >> 1)) {
#pragma unroll
            for (int u = 0; u < 8; u++)
                s_tei[u] = (i & 1) ? te[u].y : te[u].x;
        }
        __syncthreads();

        // ---- main state update + fused dv matvec ----
        {
            float2 w2 = ((const float2*)s_wv)[tid];
            float2 b2 = ((const float2*)s_bv)[tid];
            float2 l2 = ((const float2*)s_lo)[tid];
            float2 u2 = ((const float2*)s_up)[tid];
            float2 aa = ((const float2*)s_al)[tid];
#pragma unroll
            for (int u = 0; u < 8; u++) {
                float2 hnj = ((const float2*)(hn_buf + u * Hd))[tid];
                hj[u] = hnj;
                float hni = s_hni[u], tei = s_tei[u];
                float tauE = s_tauE[u], tauU = s_tauU[u], mU = s_mU[u];
                float2 tn = te[u];
                float ox = hni * tn.x - tei * hnj.x;
                float oy = hni * tn.y - tei * hnj.y;
                float2 E = ((float2*)stE)[u * 256 + tid];
                E.x += tauE * (ox - E.x);
                E.y += tauE * (oy - E.y);
                ((float2*)stE)[u * 256 + tid] = E;
                float yx = fmaf(mU, w2.x, b2.x);
                float yy = fmaf(mU, w2.y, b2.y);
                float sx = (yx > 0.5f) ? yx - 0.5f : ((yx < -0.5f) ? yx + 0.5f : 0.f);
                float sy = (yy > 0.5f) ? yy - 0.5f : ((yy < -0.5f) ? yy + 0.5f : 0.f);
                float2 D = ((float2*)sdU)[u * 256 + tid];
                D.x += tauU * (sx * E.x - D.x);
                D.y += tauU * (sy * E.y - D.y);
                D.x = fminf(fmaxf(D.x, l2.x), u2.x);
                D.y = fminf(fmaxf(D.y, l2.y), u2.y);
                ((float2*)sdU)[u * 256 + tid] = D;
                acc[u] = aa.x * D.x * hnj.x + aa.y * D.y * hnj.y;
            }
        }
#pragma unroll
        for (int u = 0; u < 8; u++) {
            float v = acc[u];
#pragma unroll
            for (int o = 16; o; o >>= 1) v += __shfl_xor_sync(0xffffffffu, v, o);
            if (lane == 0) s_red[wb][u] = v;
        }
        __syncthreads();
        if (tid < 8) {
            float s = 0.f;
#pragma unroll
            for (int w2i = 0; w2i < 8; w2i++) s += s_red[w2i][tid];
            s_dvacc[tid] = s;
        }
        __syncthreads();

        hc = hn_buf;
    }

    // ---- epilogue: dump final state ----
    if (tid < 8) {
        out[OFF_V + tid * Hd + i] = sv[tid];
        out[OFF_H + tid * Hd + i] = s_hni[tid];
    }
#pragma unroll
    for (int u = 0; u < 8; u++) {
        ((float2*)(out + OFF_DU  + (u * Hd + i) * Hd))[tid] = ((float2*)sdU)[u * 256 + tid];
        ((float2*)(out + OFF_TEE + (u * Hd + i) * Hd))[tid] = ((float2*)stE)[u * 256 + tid];
    }
    if (i == 0) {
#pragma unroll
        for (int u = 0; u < 8; u++)
            ((float2*)(out + OFF_TE + u * Hd))[tid] = te[u];
    }
}

extern "C" void kernel_launch(void* const* d_in, const int* in_sizes, int n_in,
                              void* d_out, int out_size) {
    const float* x       = (const float*)d_in[0];
    const float* h0      = (const float*)d_in[1];
    const float* v0      = (const float*)d_in[2];
    const float* dU0     = (const float*)d_in[3];
    const float* te0     = (const float*)d_in[4];
    const float* tE0     = (const float*)d_in[5];
    const float* x2h_v   = (const float*)d_in[6];
    const float* x2h_g   = (const float*)d_in[7];
    const float* x2h_b   = (const float*)d_in[8];
    const float* h2h_v   = (const float*)d_in[9];
    const float* h2h_g   = (const float*)d_in[10];
    const float* h2h_b   = (const float*)d_in[11];
    const float* alpha   = (const float*)d_in[12];
    const float* h2mod_w = (const float*)d_in[13];
    const float* h2mod_b = (const float*)d_in[14];
    const float* modU_w  = (const float*)d_in[15];
    const float* modU_b  = (const float*)d_in[16];
    float* out = (float*)d_out;

    const int scan_smem = 13824 * sizeof(float); // 55296 B
    cudaFuncSetAttribute(k_scan, cudaFuncAttributeMaxDynamicSharedMemorySize, scan_smem);

    k_xproj<<<dim3(6, 32), 256>>>(x, x2h_v, x2h_g, x2h_b);
    k_scan<<<NBLK, 256, scan_smem>>>(h0, v0, dU0, te0, tE0, alpha,
                                     h2h_v, h2h_g, h2h_b,
                                     h2mod_w, h2mod_b, modU_w, modU_b, out);
}

// round 8
// speedup vs baseline: 3.8023x; 1.2844x over previous
#include <cuda_runtime.h>
#include <math.h>

#define Td 32
#define Bd 8
#define Id 512
#define Hd 512
#define H3 1536
#define NBLK 512

// ---- output layout (concatenated tuple: v, h, dU, te, tE, outs) ----
#define OFF_V    0
#define OFF_H    4096
#define OFF_DU   8192
#define OFF_TE   2105344
#define OFF_TEE  2109440
#define OFF_OUTS 4206592

// ---- scratch (device globals; no allocation allowed) ----
__device__ float g_xproj[Td * Bd * H3]; // 1.5 MB (middle third unused)
__device__ float g_hbuf[2][Bd * Hd];    // ping-pong hidden state
__device__ unsigned g_count = 0;
__device__ unsigned g_flag[16 * 32];    // 16 broadcast flags, 128B apart
__device__ float g_gates[4][32];        // rotating gate accumulators [t&3][b*4+g]

// ============================================================
// xproj for z and dv chunks only (r chunk is dead in the reference).
// n in [0,512) u [1024,1536). Weight-norm fused.
// Grid (4, 32): 256 n per block, 8 m rows per block.
// ============================================================
__global__ void __launch_bounds__(256) k_xproj(const float* __restrict__ x,
                                               const float* __restrict__ x2h_v,
                                               const float* __restrict__ x2h_g,
                                               const float* __restrict__ x2h_b) {
    __shared__ float xs[8 * 512]; // 16 KB
    int n = (blockIdx.x < 2) ? (blockIdx.x * 256 + threadIdx.x)
                             : (1024 + (blockIdx.x - 2) * 256 + threadIdx.x);
    int m0 = blockIdx.y * 8;
    for (int idx = threadIdx.x; idx < 8 * 512; idx += 256)
        xs[idx] = x[(m0 + (idx >> 9)) * 512 + (idx & 511)];
    __syncthreads();
    float acc[8];
#pragma unroll
    for (int m = 0; m < 8; m++) acc[m] = 0.f;
    float ss = 0.f;
    const float4* wrow4 = (const float4*)(x2h_v + n * 512);
    for (int c = 0; c < 128; c++) {
        float4 w4 = wrow4[c];
        ss = fmaf(w4.x, w4.x, ss); ss = fmaf(w4.y, w4.y, ss);
        ss = fmaf(w4.z, w4.z, ss); ss = fmaf(w4.w, w4.w, ss);
#pragma unroll
        for (int m = 0; m < 8; m++) {
            float4 x4 = ((const float4*)(xs + m * 512))[c];
            acc[m] = fmaf(w4.x, x4.x, acc[m]);
            acc[m] = fmaf(w4.y, x4.y, acc[m]);
            acc[m] = fmaf(w4.z, x4.z, acc[m]);
            acc[m] = fmaf(w4.w, x4.w, acc[m]);
        }
    }
    float sc = x2h_g[n] * rsqrtf(ss);
    float bb = x2h_b[n];
#pragma unroll
    for (int m = 0; m < 8; m++)
        g_xproj[(m0 + m) * H3 + n] = fmaf(acc[m], sc, bb);
}

// ============================================================
// Grid-wide software barrier. Release fence on entry; acquire side is
// handled by __ldcg on all cross-block data (no trailing L1 flush).
// ============================================================
__device__ __forceinline__ void grid_bar(unsigned &lgen, int fidx) {
    __syncthreads();
    __threadfence();
    if (threadIdx.x == 0) {
        unsigned a = atomicAdd(&g_count, 1u);
        if (a == NBLK - 1u) {
            g_count = 0u;
            __threadfence();
#pragma unroll
            for (int f = 0; f < 16; f++)
                ((volatile unsigned*)g_flag)[f * 32] = lgen + 1u;
        } else {
            volatile unsigned* vf = &g_flag[fidx * 32];
            while (*vf == lgen) { }
        }
        lgen += 1u;
    }
    __syncthreads();
}

__device__ __forceinline__ float sigf(float x) { return 1.f / (1.f + __expf(-x)); }

// ============================================================
// Persistent scan. Block i owns dU[:,i,:], tE[:,i,:] in dynamic SMEM.
// Gates are assembled by pre-barrier atomicAdd of per-block contributions
// (h2mod_w[g,i] * hn[b,i]) — no per-block gate dot at all.
// ============================================================
__global__ void __launch_bounds__(256, 4) k_scan(
    const float* __restrict__ h0, const float* __restrict__ v0,
    const float* __restrict__ dU0, const float* __restrict__ te0,
    const float* __restrict__ tE0, const float* __restrict__ alpha,
    const float* __restrict__ h2h_v, const float* __restrict__ h2h_g,
    const float* __restrict__ h2h_b, const float* __restrict__ h2mod_w,
    const float* __restrict__ h2mod_b, const float* __restrict__ modU_w,
    const float* __restrict__ modU_b, float* __restrict__ out)
{
    extern __shared__ float sm[];
    float* sdU  = sm;             // 4096
    float* stE  = sdU + 4096;     // 4096
    float* s_al = stE + 4096;     // 512
    float* s_wv = s_al + 512;     // 512
    float* s_bv = s_wv + 512;     // 512
    float* s_lo = s_bv + 512;     // 512
    float* s_up = s_lo + 512;     // 512
    float* s_wz = s_up + 512;     // 512 (normalized Wh row i)
    float* s_wd = s_wz + 512;     // 512 (normalized Wh row 2H+i)
    // total 11776 floats = 47104 B

    __shared__ float sv[8], s_dvacc[8], s_hni[8], s_tei[8];
    __shared__ float s_g[32];      // transformed gates [b*4+g]
    __shared__ float s_red[8][8];
    __shared__ float s_sc[3];
    __shared__ float s_mw4[4];     // h2mod_w[g, i]
    __shared__ float s_mb[4];      // h2mod_b

    const int i = blockIdx.x;
    const int tid = threadIdx.x;
    const int wb = tid >> 5, lane = tid & 31;
    const int fidx = blockIdx.x & 15;
    unsigned lgen = ((volatile unsigned*)g_flag)[fidx * 32];

    const float bz = h2h_b[i];
    const float bd = h2h_b[2 * Hd + i];
    if (tid < 4) {
        s_mw4[tid] = h2mod_w[tid * 512 + i];
        s_mb[tid]  = h2mod_b[tid];
    }

    // ---- inline weight-norm of own 3 h2h rows ----
    float2 vz2 = ((const float2*)(h2h_v + i * Hd))[tid];
    float2 vr2 = ((const float2*)(h2h_v + (Hd + i) * Hd))[tid];
    float2 vd2 = ((const float2*)(h2h_v + (2 * Hd + i) * Hd))[tid];
    {
        float sz = vz2.x * vz2.x + vz2.y * vz2.y;
        float sr = vr2.x * vr2.x + vr2.y * vr2.y;
        float sd = vd2.x * vd2.x + vd2.y * vd2.y;
#pragma unroll
        for (int o = 16; o; o >>= 1) {
            sz += __shfl_xor_sync(0xffffffffu, sz, o);
            sr += __shfl_xor_sync(0xffffffffu, sr, o);
            sd += __shfl_xor_sync(0xffffffffu, sd, o);
        }
        if (lane == 0) { s_red[wb][0] = sz; s_red[wb][1] = sr; s_red[wb][2] = sd; }
    }
    __syncthreads();
    if (tid < 3) {
        float s = 0.f;
#pragma unroll
        for (int w2 = 0; w2 < 8; w2++) s += s_red[w2][tid];
        int row = (tid == 0) ? i : ((tid == 1) ? (Hd + i) : (2 * Hd + i));
        s_sc[tid] = h2h_g[row] * rsqrtf(s);
    }
    __syncthreads();
    {
        float scz = s_sc[0], scr = s_sc[1], scd = s_sc[2];
        ((float2*)s_wz)[tid] = make_float2(vz2.x * scz, vz2.y * scz);
        ((float2*)s_wd)[tid] = make_float2(vd2.x * scd, vd2.y * scd);
        float2 a2 = ((const float2*)(alpha + i * Hd))[tid];
        ((float2*)s_al)[tid] = a2;
        ((float2*)s_wv)[tid] = ((const float2*)(modU_w + i * Hd))[tid];
        ((float2*)s_bv)[tid] = ((const float2*)(modU_b + i * Hd))[tid];
        float wrx = vr2.x * scr, wry = vr2.y * scr;
        float ax = a2.x + 1e-5f, ay = a2.y + 1e-5f;
        ((float2*)s_up)[tid] = make_float2(fmaxf(1.f - wrx, 0.f) / ax,
                                           fmaxf(1.f - wry, 0.f) / ay);
        ((float2*)s_lo)[tid] = make_float2(-fmaxf(1.f + wrx, 0.f) / ax,
                                           -fmaxf(1.f + wry, 0.f) / ay);
    }

    // ---- state init ----
    float2 te[8], hj[8];
    float acc[8];
    {
        float2 a2 = ((const float2*)s_al)[tid];
#pragma unroll
        for (int u = 0; u < 8; u++) {
            float2 d2 = ((const float2*)(dU0 + (u * Hd + i) * Hd))[tid];
            ((float2*)sdU)[u * 256 + tid] = d2;
            ((float2*)stE)[u * 256 + tid] = ((const float2*)(tE0 + (u * Hd + i) * Hd))[tid];
            te[u] = ((const float2*)(te0 + u * Hd))[tid];
            hj[u] = ((const float2*)(h0 + u * Hd))[tid];
            acc[u] = a2.x * d2.x * hj[u].x + a2.y * d2.y * hj[u].y;
        }
    }
    if (tid < 8) sv[tid] = v0[tid * Hd + i];
#pragma unroll
    for (int u = 0; u < 8; u++) {
        float v = acc[u];
#pragma unroll
        for (int o = 16; o; o >>= 1) v += __shfl_xor_sync(0xffffffffu, v, o);
        if (lane == 0) s_red[wb][u] = v;
    }
    __syncthreads();
    if (tid < 8) {
        float s = 0.f;
#pragma unroll
        for (int w2 = 0; w2 < 8; w2++) s += s_red[w2][tid];
        s_dvacc[tid] = s;
    }
    __syncthreads();

    const float* hc = h0;

    for (int t = 0; t < Td; t++) {
        float* hn_buf = g_hbuf[t & 1];

        // ---- phase A: hn[b,i] (warp wb = batch b) ----
        {
            float xpz = 0.f, xpd = 0.f, dvac = 0.f, vo = 0.f;
            if (lane == 0) {
                const float* xp = g_xproj + (t * Bd + wb) * H3;
                xpz = __ldcg(xp + i);
                xpd = __ldcg(xp + 2 * Hd + i);
                dvac = s_dvacc[wb]; vo = sv[wb];
            }
            const float4* hb4 = (const float4*)(hc + wb * Hd);
            float az = 0.f, ad = 0.f;
#pragma unroll
            for (int it = 0; it < 4; it++) {
                float4 h4 = __ldcg(hb4 + lane + 32 * it);
                float4 a4 = ((const float4*)s_wz)[lane + 32 * it];
                float4 c4 = ((const float4*)s_wd)[lane + 32 * it];
                az = fmaf(a4.x, h4.x, az); az = fmaf(a4.y, h4.y, az);
                az = fmaf(a4.z, h4.z, az); az = fmaf(a4.w, h4.w, az);
                ad = fmaf(c4.x, h4.x, ad); ad = fmaf(c4.y, h4.y, ad);
                ad = fmaf(c4.z, h4.z, ad); ad = fmaf(c4.w, h4.w, ad);
            }
#pragma unroll
            for (int o = 16; o; o >>= 1) {
                az += __shfl_xor_sync(0xffffffffu, az, o);
                ad += __shfl_xor_sync(0xffffffffu, ad, o);
            }
            if (lane == 0) {
                float z  = sigf(xpz + az + bz);
                float dv = xpd + ad + bd + dvac;
                float vn = vo + z * (dv - vo);
                sv[wb] = vn;
                float hn = fmaxf(vn, 0.f);
                s_hni[wb] = hn;
                hn_buf[wb * Hd + i] = hn;
                out[OFF_OUTS + (t * Bd + wb) * Hd + i] = hn;
            }
        }
        __syncthreads();
        // post this block's gate contributions: mw[g,i] * hn[b,i]
        if (tid < 32)
            atomicAdd(&g_gates[t & 3][tid], s_mw4[tid & 3] * s_hni[tid >> 2]);

        grid_bar(lgen, fidx);

        // ---- gates: read finished sums, apply activations ----
        if (tid < 32) {
            float v = __ldcg(&g_gates[t & 3][tid]) + s_mb[tid & 3];
            s_g[tid] = ((tid & 3) == 3) ? fmaxf(v, 0.f) : sigf(v);
        }
        // block 0 zeroes the buffer that will be used at step t+2
        if (i == 0 && tid >= 64 && tid < 96)
            g_gates[(t + 2) & 3][tid - 64] = 0.f;
        __syncthreads();

        // ---- te update (register-local; OLD h carried in hj) ----
#pragma unroll
        for (int u = 0; u < 8; u++) {
            float taue = s_g[u * 4 + 0];
            float2 t2 = te[u], h2 = hj[u];
            t2.x += taue * (h2.x - t2.x);
            t2.y += taue * (h2.y - t2.y);
            te[u] = t2;
        }
        if (tid == (i >> 1)) {
#pragma unroll
            for (int u = 0; u < 8; u++)
                s_tei[u] = (i & 1) ? te[u].y : te[u].x;
        }
        __syncthreads();

        // ---- main state update + fused dv matvec ----
        {
            float2 w2 = ((const float2*)s_wv)[tid];
            float2 b2 = ((const float2*)s_bv)[tid];
            float2 l2 = ((const float2*)s_lo)[tid];
            float2 u2 = ((const float2*)s_up)[tid];
            float2 aa = ((const float2*)s_al)[tid];
#pragma unroll
            for (int u = 0; u < 8; u++) {
                float2 hnj = __ldcg((const float2*)(hn_buf + u * Hd) + tid);
                hj[u] = hnj;
                float hni = s_hni[u], tei = s_tei[u];
                float tauE = s_g[u * 4 + 1], tauU = s_g[u * 4 + 2], mU = s_g[u * 4 + 3];
                float2 tn = te[u];
                float ox = hni * tn.x - tei * hnj.x;
                float oy = hni * tn.y - tei * hnj.y;
                float2 E = ((float2*)stE)[u * 256 + tid];
                E.x += tauE * (ox - E.x);
                E.y += tauE * (oy - E.y);
                ((float2*)stE)[u * 256 + tid] = E;
                float yx = fmaf(mU, w2.x, b2.x);
                float yy = fmaf(mU, w2.y, b2.y);
                float sx = (yx > 0.5f) ? yx - 0.5f : ((yx < -0.5f) ? yx + 0.5f : 0.f);
                float sy = (yy > 0.5f) ? yy - 0.5f : ((yy < -0.5f) ? yy + 0.5f : 0.f);
                float2 D = ((float2*)sdU)[u * 256 + tid];
                D.x += tauU * (sx * E.x - D.x);
                D.y += tauU * (sy * E.y - D.y);
                D.x = fminf(fmaxf(D.x, l2.x), u2.x);
                D.y = fminf(fmaxf(D.y, l2.y), u2.y);
                ((float2*)sdU)[u * 256 + tid] = D;
                acc[u] = aa.x * D.x * hnj.x + aa.y * D.y * hnj.y;
            }
        }
#pragma unroll
        for (int u = 0; u < 8; u++) {
            float v = acc[u];
#pragma unroll
            for (int o = 16; o; o >>= 1) v += __shfl_xor_sync(0xffffffffu, v, o);
            if (lane == 0) s_red[wb][u] = v;
        }
        __syncthreads();
        if (tid < 8) {
            float s = 0.f;
#pragma unroll
            for (int w2i = 0; w2i < 8; w2i++) s += s_red[w2i][tid];
            s_dvacc[tid] = s;
        }
        __syncthreads();

        hc = hn_buf;
    }

    // ---- epilogue: dump final state ----
    if (tid < 8) {
        out[OFF_V + tid * Hd + i] = sv[tid];
        out[OFF_H + tid * Hd + i] = s_hni[tid];
    }
#pragma unroll
    for (int u = 0; u < 8; u++) {
        ((float2*)(out + OFF_DU  + (u * Hd + i) * Hd))[tid] = ((float2*)sdU)[u * 256 + tid];
        ((float2*)(out + OFF_TEE + (u * Hd + i) * Hd))[tid] = ((float2*)stE)[u * 256 + tid];
    }
    if (i == 0) {
#pragma unroll
        for (int u = 0; u < 8; u++)
            ((float2*)(out + OFF_TE + u * Hd))[tid] = te[u];
    }
}

extern "C" void kernel_launch(void* const* d_in, const int* in_sizes, int n_in,
                              void* d_out, int out_size) {
    const float* x       = (const float*)d_in[0];
    const float* h0      = (const float*)d_in[1];
    const float* v0      = (const float*)d_in[2];
    const float* dU0     = (const float*)d_in[3];
    const float* te0     = (const float*)d_in[4];
    const float* tE0     = (const float*)d_in[5];
    const float* x2h_v   = (const float*)d_in[6];
    const float* x2h_g   = (const float*)d_in[7];
    const float* x2h_b   = (const float*)d_in[8];
    const float* h2h_v   = (const float*)d_in[9];
    const float* h2h_g   = (const float*)d_in[10];
    const float* h2h_b   = (const float*)d_in[11];
    const float* alpha   = (const float*)d_in[12];
    const float* h2mod_w = (const float*)d_in[13];
    const float* h2mod_b = (const float*)d_in[14];
    const float* modU_w  = (const float*)d_in[15];
    const float* modU_b  = (const float*)d_in[16];
    float* out = (float*)d_out;

    const int scan_smem = 11776 * sizeof(float); // 47104 B
    cudaFuncSetAttribute(k_scan, cudaFuncAttributeMaxDynamicSharedMemorySize, scan_smem);

    k_xproj<<<dim3(4, 32), 256>>>(x, x2h_v, x2h_g, x2h_b);
    k_scan<<<NBLK, 256, scan_smem>>>(h0, v0, dU0, te0, tE0, alpha,
                                     h2h_v, h2h_g, h2h_b,
                                     h2mod_w, h2mod_b, modU_w, modU_b, out);
}

// round 9
// speedup vs baseline: 4.0890x; 1.0754x over previous
#include <cuda_runtime.h>
#include <math.h>

#define Td 32
#define Bd 8
#define Id 512
#define Hd 512
#define H3 1536
#define NBLK 256

// ---- output layout (concatenated tuple: v, h, dU, te, tE, outs) ----
#define OFF_V    0
#define OFF_H    4096
#define OFF_DU   8192
#define OFF_TE   2105344
#define OFF_TEE  2109440
#define OFF_OUTS 4206592

// ---- scratch (device globals; no allocation allowed) ----
__device__ float g_xproj[Td * Bd * H3]; // 1.5 MB (middle third unused)
__device__ float g_hbuf[2][Bd * Hd];    // ping-pong hidden state
__device__ unsigned g_count = 0;
__device__ unsigned g_flag[16 * 32];    // 16 broadcast flags, 128B apart
__device__ float g_gates[4][32];        // rotating gate accumulators [t&3][b*4+g]

// ============================================================
// xproj for z and dv chunks only (r chunk is dead in the reference).
// ============================================================
__global__ void __launch_bounds__(256) k_xproj(const float* __restrict__ x,
                                               const float* __restrict__ x2h_v,
                                               const float* __restrict__ x2h_g,
                                               const float* __restrict__ x2h_b) {
    __shared__ float xs[8 * 512]; // 16 KB
    int n = (blockIdx.x < 2) ? (blockIdx.x * 256 + threadIdx.x)
                             : (1024 + (blockIdx.x - 2) * 256 + threadIdx.x);
    int m0 = blockIdx.y * 8;
    for (int idx = threadIdx.x; idx < 8 * 512; idx += 256)
        xs[idx] = x[(m0 + (idx >> 9)) * 512 + (idx & 511)];
    __syncthreads();
    float acc[8];
#pragma unroll
    for (int m = 0; m < 8; m++) acc[m] = 0.f;
    float ss = 0.f;
    const float4* wrow4 = (const float4*)(x2h_v + n * 512);
#pragma unroll 2
    for (int c = 0; c < 128; c++) {
        float4 w4 = wrow4[c];
        ss = fmaf(w4.x, w4.x, ss); ss = fmaf(w4.y, w4.y, ss);
        ss = fmaf(w4.z, w4.z, ss); ss = fmaf(w4.w, w4.w, ss);
#pragma unroll
        for (int m = 0; m < 8; m++) {
            float4 x4 = ((const float4*)(xs + m * 512))[c];
            acc[m] = fmaf(w4.x, x4.x, acc[m]);
            acc[m] = fmaf(w4.y, x4.y, acc[m]);
            acc[m] = fmaf(w4.z, x4.z, acc[m]);
            acc[m] = fmaf(w4.w, x4.w, acc[m]);
        }
    }
    float sc = x2h_g[n] * rsqrtf(ss);
    float bb = x2h_b[n];
#pragma unroll
    for (int m = 0; m < 8; m++)
        g_xproj[(m0 + m) * H3 + n] = fmaf(acc[m], sc, bb);
}

// ============================================================
// Grid-wide software barrier (NBLK participants).
// ============================================================
__device__ __forceinline__ void grid_bar(unsigned &lgen, int fidx) {
    __syncthreads();
    __threadfence();
    if (threadIdx.x == 0) {
        unsigned a = atomicAdd(&g_count, 1u);
        if (a == NBLK - 1u) {
            g_count = 0u;
            __threadfence();
#pragma unroll
            for (int f = 0; f < 16; f++)
                ((volatile unsigned*)g_flag)[f * 32] = lgen + 1u;
        } else {
            volatile unsigned* vf = &g_flag[fidx * 32];
            while (*vf == lgen) { }
        }
        lgen += 1u;
    }
    __syncthreads();
}

__device__ __forceinline__ float sigf(float x) { return 1.f / (1.f + __expf(-x)); }
__device__ __forceinline__ float sshr(float y) {
    return (y > 0.5f) ? y - 0.5f : ((y < -0.5f) ? y + 0.5f : 0.f);
}

// ============================================================
// Persistent scan: 256 blocks own 2 rows each (iA=blk, iB=blk+256).
// Row A dU/tE in SMEM, row B dU/tE in REGISTERS. hn staged into SMEM
// once per step and reused by both the update and next step's matvec.
// ============================================================
__global__ void __launch_bounds__(256, 2) k_scan(
    const float* __restrict__ h0, const float* __restrict__ v0,
    const float* __restrict__ dU0, const float* __restrict__ te0,
    const float* __restrict__ tE0, const float* __restrict__ alpha,
    const float* __restrict__ h2h_v, const float* __restrict__ h2h_g,
    const float* __restrict__ h2h_b, const float* __restrict__ h2mod_w,
    const float* __restrict__ h2mod_b, const float* __restrict__ modU_w,
    const float* __restrict__ modU_b, float* __restrict__ out)
{
    extern __shared__ float sm[];
    float* s_hn  = sm;             // 4096 (current h, staged)
    float* sdU   = s_hn + 4096;    // 4096 (row A)
    float* stE   = sdU + 4096;     // 4096 (row A)
    float* s_wzA = stE + 4096;     // 512
    float* s_wdA = s_wzA + 512;    // 512
    float* s_wzB = s_wdA + 512;    // 512
    float* s_wdB = s_wzB + 512;    // 512
    // total 14336 floats = 57344 B

    __shared__ float sv[16], s_dvacc[16];
    __shared__ float s_hniA[8], s_hniB[8], s_teiA[8], s_teiB[8];
    __shared__ float s_g[32];
    __shared__ float s_red[8][16];
    __shared__ float s_sc[6];
    __shared__ float s_mw8[8], s_mb[4];

    const int iA = blockIdx.x, iB = iA + 256;
    const int tid = threadIdx.x;
    const int wb = tid >> 5, lane = tid & 31;
    const int fidx = blockIdx.x & 15;
    unsigned lgen = ((volatile unsigned*)g_flag)[fidx * 32];

    if (tid < 8) s_mw8[tid] = h2mod_w[(tid & 3) * 512 + ((tid < 4) ? iA : iB)];
    if (tid < 4) s_mb[tid] = h2mod_b[tid];
    const float bzA = h2h_b[iA], bdA = h2h_b[2 * Hd + iA];
    const float bzB = h2h_b[iB], bdB = h2h_b[2 * Hd + iB];

    // ---- inline weight-norm: 6 h2h rows (z/r/d for iA and iB) ----
    float2 vzA = ((const float2*)(h2h_v + iA * Hd))[tid];
    float2 vrA = ((const float2*)(h2h_v + (Hd + iA) * Hd))[tid];
    float2 vdA = ((const float2*)(h2h_v + (2 * Hd + iA) * Hd))[tid];
    float2 vzB = ((const float2*)(h2h_v + iB * Hd))[tid];
    float2 vrB = ((const float2*)(h2h_v + (Hd + iB) * Hd))[tid];
    float2 vdB = ((const float2*)(h2h_v + (2 * Hd + iB) * Hd))[tid];
    {
        float s0 = vzA.x * vzA.x + vzA.y * vzA.y;
        float s1 = vrA.x * vrA.x + vrA.y * vrA.y;
        float s2 = vdA.x * vdA.x + vdA.y * vdA.y;
        float s3 = vzB.x * vzB.x + vzB.y * vzB.y;
        float s4 = vrB.x * vrB.x + vrB.y * vrB.y;
        float s5 = vdB.x * vdB.x + vdB.y * vdB.y;
#pragma unroll
        for (int o = 16; o; o >>= 1) {
            s0 += __shfl_xor_sync(0xffffffffu, s0, o);
            s1 += __shfl_xor_sync(0xffffffffu, s1, o);
            s2 += __shfl_xor_sync(0xffffffffu, s2, o);
            s3 += __shfl_xor_sync(0xffffffffu, s3, o);
            s4 += __shfl_xor_sync(0xffffffffu, s4, o);
            s5 += __shfl_xor_sync(0xffffffffu, s5, o);
        }
        if (lane == 0) {
            s_red[wb][0] = s0; s_red[wb][1] = s1; s_red[wb][2] = s2;
            s_red[wb][3] = s3; s_red[wb][4] = s4; s_red[wb][5] = s5;
        }
    }
    __syncthreads();
    if (tid < 6) {
        float s = 0.f;
#pragma unroll
        for (int w2 = 0; w2 < 8; w2++) s += s_red[w2][tid];
        int col = (tid < 3) ? iA : iB;
        int row = (tid % 3) * Hd + col;
        s_sc[tid] = h2h_g[row] * rsqrtf(s);
    }
    __syncthreads();

    // per-row constants into registers (+ wz/wd into smem)
    float2 alA, alB, wvA, wvB, bvA, bvB, loA, loB, upA, upB;
    {
        ((float2*)s_wzA)[tid] = make_float2(vzA.x * s_sc[0], vzA.y * s_sc[0]);
        ((float2*)s_wdA)[tid] = make_float2(vdA.x * s_sc[2], vdA.y * s_sc[2]);
        ((float2*)s_wzB)[tid] = make_float2(vzB.x * s_sc[3], vzB.y * s_sc[3]);
        ((float2*)s_wdB)[tid] = make_float2(vdB.x * s_sc[5], vdB.y * s_sc[5]);
        alA = ((const float2*)(alpha + iA * Hd))[tid];
        alB = ((const float2*)(alpha + iB * Hd))[tid];
        wvA = ((const float2*)(modU_w + iA * Hd))[tid];
        wvB = ((const float2*)(modU_w + iB * Hd))[tid];
        bvA = ((const float2*)(modU_b + iA * Hd))[tid];
        bvB = ((const float2*)(modU_b + iB * Hd))[tid];
        float wrx = vrA.x * s_sc[1], wry = vrA.y * s_sc[1];
        float ax = alA.x + 1e-5f, ay = alA.y + 1e-5f;
        upA = make_float2(fmaxf(1.f - wrx, 0.f) / ax, fmaxf(1.f - wry, 0.f) / ay);
        loA = make_float2(-fmaxf(1.f + wrx, 0.f) / ax, -fmaxf(1.f + wry, 0.f) / ay);
        wrx = vrB.x * s_sc[4]; wry = vrB.y * s_sc[4];
        ax = alB.x + 1e-5f; ay = alB.y + 1e-5f;
        upB = make_float2(fmaxf(1.f - wrx, 0.f) / ax, fmaxf(1.f - wry, 0.f) / ay);
        loB = make_float2(-fmaxf(1.f + wrx, 0.f) / ax, -fmaxf(1.f + wry, 0.f) / ay);
    }

    // ---- stage h0 and init state ----
    for (int idx = tid; idx < 1024; idx += 256)
        ((float4*)s_hn)[idx] = ((const float4*)h0)[idx];

    float2 te[8], dUB[8], tEB[8];
#pragma unroll
    for (int u = 0; u < 8; u++) {
        float2 dA = ((const float2*)(dU0 + (u * Hd + iA) * Hd))[tid];
        ((float2*)sdU)[u * 256 + tid] = dA;
        ((float2*)stE)[u * 256 + tid] = ((const float2*)(tE0 + (u * Hd + iA) * Hd))[tid];
        dUB[u] = ((const float2*)(dU0 + (u * Hd + iB) * Hd))[tid];
        tEB[u] = ((const float2*)(tE0 + (u * Hd + iB) * Hd))[tid];
        te[u] = ((const float2*)(te0 + u * Hd))[tid];
        float2 h2 = ((const float2*)(h0 + u * Hd))[tid];
        float accA = alA.x * dA.x * h2.x + alA.y * dA.y * h2.y;
        float accB = alB.x * dUB[u].x * h2.x + alB.y * dUB[u].y * h2.y;
#pragma unroll
        for (int o = 16; o; o >>= 1) {
            accA += __shfl_xor_sync(0xffffffffu, accA, o);
            accB += __shfl_xor_sync(0xffffffffu, accB, o);
        }
        if (lane == 0) { s_red[wb][u] = accA; s_red[wb][8 + u] = accB; }
    }
    if (tid < 16) sv[tid] = v0[(tid & 7) * Hd + ((tid < 8) ? iA : iB)];
    __syncthreads();
    if (tid < 16) {
        float s = 0.f;
#pragma unroll
        for (int w2 = 0; w2 < 8; w2++) s += s_red[w2][tid];
        s_dvacc[tid] = s;
    }
    __syncthreads();

    for (int t = 0; t < Td; t++) {
        float* hn_buf = g_hbuf[t & 1];

        // ---- phase A: hn for rows iA,iB, batch wb (warp = batch) ----
        {
            float xpzA = 0.f, xpdA = 0.f, xpzB = 0.f, xpdB = 0.f;
            float dvA = 0.f, dvB = 0.f, voA = 0.f, voB = 0.f;
            if (lane == 0) {
                const float* xp = g_xproj + (t * Bd + wb) * H3;
                xpzA = __ldcg(xp + iA); xpdA = __ldcg(xp + 2 * Hd + iA);
                xpzB = __ldcg(xp + iB); xpdB = __ldcg(xp + 2 * Hd + iB);
                dvA = s_dvacc[wb]; dvB = s_dvacc[8 + wb];
                voA = sv[wb]; voB = sv[8 + wb];
            }
            const float4* hb4 = (const float4*)(s_hn + wb * Hd);
            float azA = 0.f, adA = 0.f, azB = 0.f, adB = 0.f;
#pragma unroll
            for (int it = 0; it < 4; it++) {
                float4 h4 = hb4[lane + 32 * it];
                float4 a4 = ((const float4*)s_wzA)[lane + 32 * it];
                float4 c4 = ((const float4*)s_wdA)[lane + 32 * it];
                float4 e4 = ((const float4*)s_wzB)[lane + 32 * it];
                float4 f4 = ((const float4*)s_wdB)[lane + 32 * it];
                azA = fmaf(a4.x, h4.x, azA); azA = fmaf(a4.y, h4.y, azA);
                azA = fmaf(a4.z, h4.z, azA); azA = fmaf(a4.w, h4.w, azA);
                adA = fmaf(c4.x, h4.x, adA); adA = fmaf(c4.y, h4.y, adA);
                adA = fmaf(c4.z, h4.z, adA); adA = fmaf(c4.w, h4.w, adA);
                azB = fmaf(e4.x, h4.x, azB); azB = fmaf(e4.y, h4.y, azB);
                azB = fmaf(e4.z, h4.z, azB); azB = fmaf(e4.w, h4.w, azB);
                adB = fmaf(f4.x, h4.x, adB); adB = fmaf(f4.y, h4.y, adB);
                adB = fmaf(f4.z, h4.z, adB); adB = fmaf(f4.w, h4.w, adB);
            }
#pragma unroll
            for (int o = 16; o; o >>= 1) {
                azA += __shfl_xor_sync(0xffffffffu, azA, o);
                adA += __shfl_xor_sync(0xffffffffu, adA, o);
                azB += __shfl_xor_sync(0xffffffffu, azB, o);
                adB += __shfl_xor_sync(0xffffffffu, adB, o);
            }
            if (lane == 0) {
                float z  = sigf(xpzA + azA + bzA);
                float dv = xpdA + adA + bdA + dvA;
                float vn = voA + z * (dv - voA);
                sv[wb] = vn;
                float hn = fmaxf(vn, 0.f);
                s_hniA[wb] = hn;
                hn_buf[wb * Hd + iA] = hn;
                out[OFF_OUTS + (t * Bd + wb) * Hd + iA] = hn;
                z  = sigf(xpzB + azB + bzB);
                dv = xpdB + adB + bdB + dvB;
                vn = voB + z * (dv - voB);
                sv[8 + wb] = vn;
                hn = fmaxf(vn, 0.f);
                s_hniB[wb] = hn;
                hn_buf[wb * Hd + iB] = hn;
                out[OFF_OUTS + (t * Bd + wb) * Hd + iB] = hn;
            }
        }
        __syncthreads();
        // gate contributions: mw[g,row_i] * hn[b,row_i]
        if (tid < 64) {
            int r = tid >> 5, bb = (tid >> 2) & 7, g = tid & 3;
            float hv = r ? s_hniB[bb] : s_hniA[bb];
            atomicAdd(&g_gates[t & 3][bb * 4 + g], s_mw8[r * 4 + g] * hv);
        }

        grid_bar(lgen, fidx);

        // ---- gates: read finished sums, apply activations ----
        if (tid < 32) {
            float v = __ldcg(&g_gates[t & 3][tid]) + s_mb[tid & 3];
            s_g[tid] = ((tid & 3) == 3) ? fmaxf(v, 0.f) : sigf(v);
        }
        if (iA == 0 && tid >= 64 && tid < 96)
            g_gates[(t + 2) & 3][tid - 64] = 0.f;
        __syncthreads();

        // ---- te update (uses OLD h still in s_hn) ----
#pragma unroll
        for (int u = 0; u < 8; u++) {
            float taue = s_g[u * 4 + 0];
            float2 h2 = ((const float2*)s_hn)[u * 256 + tid];
            te[u].x += taue * (h2.x - te[u].x);
            te[u].y += taue * (h2.y - te[u].y);
        }
        if (tid == (iA >> 1)) {
#pragma unroll
            for (int u = 0; u < 8; u++)
                s_teiA[u] = (iA & 1) ? te[u].y : te[u].x;
        }
        if (tid == (iB >> 1)) {
#pragma unroll
            for (int u = 0; u < 8; u++)
                s_teiB[u] = (iB & 1) ? te[u].y : te[u].x;
        }
        __syncthreads();   // old s_hn fully consumed; s_tei ready

        // ---- stage NEW hn into s_hn ----
        for (int idx = tid; idx < 1024; idx += 256)
            ((float4*)s_hn)[idx] = __ldcg((const float4*)hn_buf + idx);
        __syncthreads();

        // ---- main state update (rows A smem, B regs) + fused matvec ----
#pragma unroll
        for (int u = 0; u < 8; u++) {
            float2 hnj = ((const float2*)s_hn)[u * 256 + tid];
            float tauE = s_g[u * 4 + 1], tauU = s_g[u * 4 + 2], mU = s_g[u * 4 + 3];
            float2 tn = te[u];
            // row A
            float hni = s_hniA[u], tei = s_teiA[u];
            float ox = hni * tn.x - tei * hnj.x;
            float oy = hni * tn.y - tei * hnj.y;
            float2 E = ((float2*)stE)[u * 256 + tid];
            E.x += tauE * (ox - E.x);
            E.y += tauE * (oy - E.y);
            ((float2*)stE)[u * 256 + tid] = E;
            float2 D = ((float2*)sdU)[u * 256 + tid];
            D.x += tauU * (sshr(fmaf(mU, wvA.x, bvA.x)) * E.x - D.x);
            D.y += tauU * (sshr(fmaf(mU, wvA.y, bvA.y)) * E.y - D.y);
            D.x = fminf(fmaxf(D.x, loA.x), upA.x);
            D.y = fminf(fmaxf(D.y, loA.y), upA.y);
            ((float2*)sdU)[u * 256 + tid] = D;
            float accA = alA.x * D.x * hnj.x + alA.y * D.y * hnj.y;
            // row B (registers)
            hni = s_hniB[u]; tei = s_teiB[u];
            ox = hni * tn.x - tei * hnj.x;
            oy = hni * tn.y - tei * hnj.y;
            tEB[u].x += tauE * (ox - tEB[u].x);
            tEB[u].y += tauE * (oy - tEB[u].y);
            dUB[u].x += tauU * (sshr(fmaf(mU, wvB.x, bvB.x)) * tEB[u].x - dUB[u].x);
            dUB[u].y += tauU * (sshr(fmaf(mU, wvB.y, bvB.y)) * tEB[u].y - dUB[u].y);
            dUB[u].x = fminf(fmaxf(dUB[u].x, loB.x), upB.x);
            dUB[u].y = fminf(fmaxf(dUB[u].y, loB.y), upB.y);
            float accB = alB.x * dUB[u].x * hnj.x + alB.y * dUB[u].y * hnj.y;
#pragma unroll
            for (int o = 16; o; o >>= 1) {
                accA += __shfl_xor_sync(0xffffffffu, accA, o);
                accB += __shfl_xor_sync(0xffffffffu, accB, o);
            }
            if (lane == 0) { s_red[wb][u] = accA; s_red[wb][8 + u] = accB; }
        }
        __syncthreads();
        if (tid < 16) {
            float s = 0.f;
#pragma unroll
            for (int w2 = 0; w2 < 8; w2++) s += s_red[w2][tid];
            s_dvacc[tid] = s;
        }
        __syncthreads();
    }

    // ---- epilogue: dump final state ----
    if (tid < 16) {
        int b = tid & 7, col = (tid < 8) ? iA : iB;
        out[OFF_V + b * Hd + col] = sv[tid];
        out[OFF_H + b * Hd + col] = (tid < 8) ? s_hniA[b] : s_hniB[b];
    }
#pragma unroll
    for (int u = 0; u < 8; u++) {
        ((float2*)(out + OFF_DU  + (u * Hd + iA) * Hd))[tid] = ((float2*)sdU)[u * 256 + tid];
        ((float2*)(out + OFF_TEE + (u * Hd + iA) * Hd))[tid] = ((float2*)stE)[u * 256 + tid];
        ((float2*)(out + OFF_DU  + (u * Hd + iB) * Hd))[tid] = dUB[u];
        ((float2*)(out + OFF_TEE + (u * Hd + iB) * Hd))[tid] = tEB[u];
    }
    if (iA == 0) {
#pragma unroll
        for (int u = 0; u < 8; u++)
            ((float2*)(out + OFF_TE + u * Hd))[tid] = te[u];
    }
}

extern "C" void kernel_launch(void* const* d_in, const int* in_sizes, int n_in,
                              void* d_out, int out_size) {
    const float* x       = (const float*)d_in[0];
    const float* h0      = (const float*)d_in[1];
    const float* v0      = (const float*)d_in[2];
    const float* dU0     = (const float*)d_in[3];
    const float* te0     = (const float*)d_in[4];
    const float* tE0     = (const float*)d_in[5];
    const float* x2h_v   = (const float*)d_in[6];
    const float* x2h_g   = (const float*)d_in[7];
    const float* x2h_b   = (const float*)d_in[8];
    const float* h2h_v   = (const float*)d_in[9];
    const float* h2h_g   = (const float*)d_in[10];
    const float* h2h_b   = (const float*)d_in[11];
    const float* alpha   = (const float*)d_in[12];
    const float* h2mod_w = (const float*)d_in[13];
    const float* h2mod_b = (const float*)d_in[14];
    const float* modU_w  = (const float*)d_in[15];
    const float* modU_b  = (const float*)d_in[16];
    float* out = (float*)d_out;

    const int scan_smem = 14336 * sizeof(float); // 57344 B
    cudaFuncSetAttribute(k_scan, cudaFuncAttributeMaxDynamicSharedMemorySize, scan_smem);

    k_xproj<<<dim3(4, 32), 256>>>(x, x2h_v, x2h_g, x2h_b);
    k_scan<<<NBLK, 256, scan_smem>>>(h0, v0, dU0, te0, tE0, alpha,
                                     h2h_v, h2h_g, h2h_b,
                                     h2mod_w, h2mod_b, modU_w, modU_b, out);
}